// round 1
// baseline (speedup 1.0000x reference)
#include <cuda_runtime.h>
#include <stdint.h>

#define KPRE       500
#define MAXDET     300
#define SCORE_THR  0.05f
#define NMS_THR    0.5f
#define MIN_SIZE   0.01f
#define BBOX_CLAMP 4.135166556742356f   // log(1000/16)
#define BINS       8192
#define CAP        2048
#define NT         512
#define DYN_SMEM   57344                // keys 16KB + cbox 8KB + ioum 32KB (hist 32KB aliases)

#define BMAX 2
#define AMAX 120000
#define CMAX 80

// Scratch (static device globals — no allocation allowed)
__device__ float         g_boxes[(size_t)BMAX * AMAX * 4];
__device__ unsigned char g_valid[(size_t)BMAX * AMAX];
__device__ float         g_scores_t[(size_t)BMAX * CMAX * AMAX];

// ---------------------------------------------------------------------------
// K1: decode + clamp + valid mask
// ---------------------------------------------------------------------------
__global__ void rn_decode_kernel(const float* __restrict__ deltas,
                                 const float* __restrict__ anchors,
                                 const int* __restrict__ imh,
                                 const int* __restrict__ imw,
                                 int B, int A) {
    int i = blockIdx.x * blockDim.x + threadIdx.x;
    if (i >= B * A) return;
    float W = (float)imw[0];
    float H = (float)imh[0];
    float4 an = reinterpret_cast<const float4*>(anchors)[i];
    float4 dt = reinterpret_cast<const float4*>(deltas)[i];
    float aw  = an.z - an.x;
    float ah  = an.w - an.y;
    float acx = an.x + 0.5f * aw;
    float acy = an.y + 0.5f * ah;
    float dw  = fminf(dt.z, BBOX_CLAMP);
    float dh  = fminf(dt.w, BBOX_CLAMP);
    float pcx = dt.x * aw + acx;
    float pcy = dt.y * ah + acy;
    float pw  = expf(dw) * aw;
    float ph  = expf(dh) * ah;
    float x1 = fminf(fmaxf(pcx - 0.5f * pw, 0.0f), W);
    float y1 = fminf(fmaxf(pcy - 0.5f * ph, 0.0f), H);
    float x2 = fminf(fmaxf(pcx + 0.5f * pw, 0.0f), W);
    float y2 = fminf(fmaxf(pcy + 0.5f * ph, 0.0f), H);
    reinterpret_cast<float4*>(g_boxes)[i] = make_float4(x1, y1, x2, y2);
    g_valid[i] = (((x2 - x1) >= MIN_SIZE) && ((y2 - y1) >= MIN_SIZE)) ? 1 : 0;
}

// ---------------------------------------------------------------------------
// K2: transpose scores [B,A,C] -> [B,C,A], folding valid & score-threshold
// mask (excluded -> -1). Coalesced both ways via 32x32 SMEM tile.
// ---------------------------------------------------------------------------
__global__ void rn_transpose_kernel(const float* __restrict__ scores,
                                    int B, int A, int C) {
    __shared__ float tile[32][33];
    int b  = blockIdx.z;
    int a0 = blockIdx.x * 32;
    int c0 = blockIdx.y * 32;

    // load: threadIdx.x along C (contiguous)
    #pragma unroll
    for (int r = 0; r < 32; r += 8) {
        int a = a0 + threadIdx.y + r;
        int c = c0 + threadIdx.x;
        float v = -1.0f;
        if (a < A && c < C)
            v = scores[((size_t)b * A + a) * (size_t)C + c];
        tile[threadIdx.y + r][threadIdx.x] = v;
    }
    __syncthreads();

    // store: threadIdx.x along A (contiguous)
    int a = a0 + threadIdx.x;
    unsigned char vflag = (a < A) ? g_valid[(size_t)b * A + a] : 0;
    #pragma unroll
    for (int r = 0; r < 32; r += 8) {
        int c = c0 + threadIdx.y + r;
        if (a < A && c < C) {
            float s = tile[threadIdx.x][threadIdx.y + r];
            if (!vflag || !(s > SCORE_THR)) s = -1.0f;
            g_scores_t[((size_t)b * C + c) * (size_t)A + a] = s;
        }
    }
}

// ---------------------------------------------------------------------------
// K3: per-(b,c) top-500 selection (histogram select + exact sort), NMS, output
// ---------------------------------------------------------------------------
__global__ void __launch_bounds__(NT)
rn_nms_kernel(float* __restrict__ out, int B, int A, int C) {
    extern __shared__ unsigned char dyn[];
    unsigned int*       hist  = reinterpret_cast<unsigned int*>(dyn);         // [BINS] (phase 1)
    unsigned long long* keys  = reinterpret_cast<unsigned long long*>(dyn);   // [CAP]  (phase 2, aliases hist)
    float4*             cbox4 = reinterpret_cast<float4*>(dyn + CAP * 8);     // [KPRE]
    unsigned int*       ioum  = reinterpret_cast<unsigned int*>(dyn + CAP * 8 + KPRE * 16); // [KPRE*16]

    __shared__ unsigned int chunk[NT];
    __shared__ unsigned int s_cnt, s_T, s_nkeep;
    __shared__ unsigned int keep0[16], keepw[16], pref[16];
    __shared__ float cscore[KPRE];

    const int tid = threadIdx.x;
    const int bc  = blockIdx.x;
    const int b   = bc / C;
    const int c   = bc % C;
    const float* __restrict__ sc = g_scores_t + ((size_t)b * C + c) * (size_t)A;

    // ---- phase 1: histogram over (thr, 1] with linear bins ----
    for (int i = tid; i < BINS; i += NT) hist[i] = 0;
    if (tid == 0) s_cnt = 0;
    if (tid < 16) keep0[tid] = 0;
    __syncthreads();

    for (int a = tid; a < A; a += NT) {
        float s = sc[a];
        if (s > SCORE_THR) {
            int bin = (int)(s * (float)BINS);
            bin = min(max(bin, 0), BINS - 1);
            atomicAdd(&hist[bin], 1u);
        }
    }
    __syncthreads();

    // per-thread chunk sums (BINS/NT = 16 bins each)
    {
        unsigned int cs = 0;
        const int per = BINS / NT;
        #pragma unroll
        for (int i = 0; i < BINS / NT; i++) cs += hist[tid * per + i];
        chunk[tid] = cs;
    }
    __syncthreads();

    // single-thread suffix scan to find threshold bin T (largest bin with
    // suffix count >= KPRE; T=0 if fewer than KPRE candidates total)
    if (tid == 0) {
        const int per = BINS / NT;
        unsigned int cum = 0;
        int cc;
        for (cc = NT - 1; cc >= 0; cc--) {
            if (cum + chunk[cc] >= KPRE) break;
            cum += chunk[cc];
        }
        int T = 0;
        if (cc >= 0) {
            int base = cc * per;
            for (int bb = base + per - 1; bb >= base; bb--) {
                cum += hist[bb];
                if (cum >= KPRE) { T = bb; break; }
            }
        }
        s_T = (unsigned int)T;
    }
    __syncthreads();
    const unsigned int T = s_T;
    __syncthreads();  // all reads of hist done before keys (alias) is written

    // ---- phase 2: collect candidates with bin >= T ----
    for (int a = tid; a < A; a += NT) {
        float s = sc[a];
        if (s > SCORE_THR) {
            int bin = min((int)(s * (float)BINS), BINS - 1);
            if ((unsigned int)bin >= T) {
                unsigned int pos = atomicAdd(&s_cnt, 1u);
                if (pos < CAP) {
                    unsigned long long key =
                        ((unsigned long long)__float_as_uint(s) << 32) |
                        (unsigned long long)(0xFFFFFFFFu - (unsigned int)a);
                    keys[pos] = key;
                }
            }
        }
    }
    __syncthreads();
    unsigned int cnt = min(s_cnt, (unsigned int)CAP);
    for (int i = tid; i < CAP; i += NT)
        if (i >= (int)cnt) keys[i] = 0ULL;   // pad: score 0, invalid
    __syncthreads();

    // ---- bitonic sort descending (exact top-k w/ index tie-break) ----
    for (unsigned int k = 2; k <= CAP; k <<= 1) {
        for (unsigned int j = k >> 1; j > 0; j >>= 1) {
            for (unsigned int i = tid; i < CAP; i += NT) {
                unsigned int ixj = i ^ j;
                if (ixj > i) {
                    unsigned long long x = keys[i];
                    unsigned long long y = keys[ixj];
                    bool desc = ((i & k) == 0);
                    if (desc ? (x < y) : (x > y)) { keys[i] = y; keys[ixj] = x; }
                }
            }
            __syncthreads();
        }
    }

    // ---- candidate setup: scores, boxes, initial keep ----
    if (tid < KPRE) {
        unsigned long long key = keys[tid];
        float s = __uint_as_float((unsigned int)(key >> 32));
        unsigned int aidx = 0xFFFFFFFFu - (unsigned int)(key & 0xFFFFFFFFull);
        bool cv = (s > SCORE_THR);
        cscore[tid] = s;
        float4 bx = make_float4(0.0f, 0.0f, 0.0f, 0.0f);
        if (cv)
            bx = reinterpret_cast<const float4*>(g_boxes)[(size_t)b * A + aidx];
        cbox4[tid] = bx;
        if (cv) atomicOr(&keep0[tid >> 5], 1u << (tid & 31));
    }
    __syncthreads();

    // ---- IoU suppression bitmask: row i, bit j set iff j>i && IoU>thr ----
    for (int w = tid; w < KPRE * 16; w += NT) {
        int i  = w >> 4;
        int wi = w & 15;
        float4 bi = cbox4[i];
        float iarea = (bi.z - bi.x) * (bi.w - bi.y);
        unsigned int m = 0;
        int jbase = wi * 32;
        for (int bit = 0; bit < 32; bit++) {
            int j = jbase + bit;
            if (j < KPRE && j > i) {
                float4 bj = cbox4[j];
                float jarea = (bj.z - bj.x) * (bj.w - bj.y);
                float lx = fmaxf(bi.x, bj.x);
                float ly = fmaxf(bi.y, bj.y);
                float rx = fminf(bi.z, bj.z);
                float ry = fminf(bi.w, bj.w);
                float iw = fmaxf(rx - lx, 0.0f);
                float ih = fmaxf(ry - ly, 0.0f);
                float inter = iw * ih;
                float iou = inter / fmaxf(iarea + jarea - inter, 1e-9f);
                if (iou > NMS_THR) m |= (1u << bit);
            }
        }
        ioum[w] = m;
    }
    __syncthreads();

    // ---- serial-semantics NMS scan: 16 lanes, one keep-word each ----
    if (tid < 16) {
        unsigned int kw = keep0[tid];
        for (int i = 0; i < KPRE; i++) {
            unsigned int word = __shfl_sync(0xFFFFu, kw, i >> 5);
            if ((word >> (i & 31)) & 1u)
                kw &= ~ioum[i * 16 + tid];
        }
        keepw[tid] = kw;
        // exclusive prefix popcount across the 16 words
        unsigned int p = __popc(kw);
        unsigned int scan = p;
        #pragma unroll
        for (int o = 1; o < 16; o <<= 1) {
            unsigned int v = __shfl_up_sync(0xFFFFu, scan, o);
            if (tid >= o) scan += v;
        }
        pref[tid] = scan - p;
        if (tid == 15) s_nkeep = scan;
    }
    __syncthreads();

    // ---- output: kept (in score order) first, rest (0,0,0,0,-1) ----
    float* outp = out + (size_t)bc * MAXDET * 5;
    if (tid < KPRE) {
        unsigned int kw = keepw[tid >> 5];
        if ((kw >> (tid & 31)) & 1u) {
            unsigned int rank = pref[tid >> 5] + __popc(kw & ((1u << (tid & 31)) - 1u));
            if (rank < MAXDET) {
                float4 bx = cbox4[tid];
                outp[rank * 5 + 0] = bx.x;
                outp[rank * 5 + 1] = bx.y;
                outp[rank * 5 + 2] = bx.z;
                outp[rank * 5 + 3] = bx.w;
                outp[rank * 5 + 4] = cscore[tid];
            }
        }
    }
    unsigned int nk = min(s_nkeep, (unsigned int)MAXDET);
    for (int r = (int)nk + tid; r < MAXDET; r += NT) {
        outp[r * 5 + 0] = 0.0f;
        outp[r * 5 + 1] = 0.0f;
        outp[r * 5 + 2] = 0.0f;
        outp[r * 5 + 3] = 0.0f;
        outp[r * 5 + 4] = -1.0f;
    }
}

// ---------------------------------------------------------------------------
// host launch
// ---------------------------------------------------------------------------
extern "C" void kernel_launch(void* const* d_in, const int* in_sizes, int n_in,
                              void* d_out, int out_size) {
    const float* deltas  = (const float*)d_in[0];
    const float* scores  = (const float*)d_in[1];
    const float* anchors = (const float*)d_in[2];
    const int*   imh     = (const int*)d_in[3];
    const int*   imw     = (const int*)d_in[4];

    // shapes: deltas B*A*4, scores B*A*C, out B*C*MAXDET*5
    long long nd = in_sizes[0];
    long long ns = in_sizes[1];
    int C  = (int)(ns * 4 / nd);
    int BC = out_size / (MAXDET * 5);
    int B  = BC / C;
    int A  = (int)(nd / (4LL * B));

    float* out = (float*)d_out;

    int n = B * A;
    rn_decode_kernel<<<(n + 255) / 256, 256>>>(deltas, anchors, imh, imw, B, A);

    dim3 tb(32, 8);
    dim3 tg((A + 31) / 32, (C + 31) / 32, B);
    rn_transpose_kernel<<<tg, tb>>>(scores, B, A, C);

    cudaFuncSetAttribute(rn_nms_kernel,
                         cudaFuncAttributeMaxDynamicSharedMemorySize, DYN_SMEM);
    rn_nms_kernel<<<B * C, NT, DYN_SMEM>>>(out, B, A, C);
}